// round 16
// baseline (speedup 1.0000x reference)
#include <cuda_runtime.h>
#include <cuda_bf16.h>

#define BB 2
#define CC 128
#define TT 5
#define HH 48
#define WW 48
#define HWP 2304      // H*W
#define NH 64         // heads
#define TC 4          // context frames
#define PAD 3
#define NK 196        // Tc*7*7
#define FRAME (TC * HWP)

// Scratch (allocation-free rule: __device__ globals)
__device__ float          g_q    [BB * HWP * NH];      // [b][pix][h] fp32
__device__ __nv_bfloat16  g_phi2b[BB * TC * HWP * NH]; // [b][t][pix][h] bf16 (QK)
__device__ __nv_bfloat16  g_gvTb [BB * NH * FRAME];    // [b][h][t][pix] bf16 (AV)
__device__ float          g_z    [BB * HWP * NH];      // [b][p2][h2] (scrambled Y)
__device__ float          g_wcT  [CC * CC];            // [c][r]: r<64 phi, r>=64 g
__device__ float          g_wqT  [CC * NH];            // [c][r]: theta
__device__ float          g_woT  [NH * CC];            // [h2][c]: w_out transposed

typedef unsigned long long u64t;
__device__ __forceinline__ u64t pk2(float lo, float hi) {
    u64t r; asm("mov.b64 %0,{%1,%2};" : "=l"(r) : "f"(lo), "f"(hi)); return r;
}
__device__ __forceinline__ void upk2(u64t v, float& lo, float& hi) {
    asm("mov.b64 {%0,%1},%2;" : "=f"(lo), "=f"(hi) : "l"(v));
}
#define FMA2(d, a, b, c) asm("fma.rn.f32x2 %0,%1,%2,%3;" : "=l"(d) : "l"(a), "l"(b), "l"(c))

// ---------------------------------------------------------------------------
// One-time weight transposes (coalesced reads, scattered stores absorbed).
// ---------------------------------------------------------------------------
__global__ __launch_bounds__(256) void wtrans_kernel(
        const float* __restrict__ wt,
        const float* __restrict__ wp,
        const float* __restrict__ wg,
        const float* __restrict__ wo) {
    int i = blockIdx.x * 256 + threadIdx.x;
    if (i < NH * CC) {                    // phi
        int r = i >> 7, c = i & 127;
        g_wcT[c * CC + r] = wp[i];
    } else if (i < 2 * NH * CC) {         // g
        int j = i - NH * CC;
        int r = j >> 7, c = j & 127;
        g_wcT[c * CC + NH + r] = wg[j];
    } else if (i < 3 * NH * CC) {         // theta
        int j = i - 2 * NH * CC;
        int r = j >> 7, c = j & 127;
        g_wqT[c * NH + r] = wt[j];
    } else {                              // w_out [CC][NH] -> [NH][CC]
        int j = i - 3 * NH * CC;
        int c = j >> 6, h2 = j & 63;
        g_woT[h2 * CC + c] = wo[j];
    }
}

// ---------------------------------------------------------------------------
// Merged projections, 256 threads/block (2x warps vs R15 for latency cover).
// blocks [0, 576): ctx — thread (r = tid&127, ph = tid>>7) computes 16 px.
//   phi rows (r<64) -> g_phi2b bf16 [b][t][pix][h]
//   g   rows        -> g_gvTb  bf16 [b][h][t][pix]
// blocks [576, 720): theta — thread (r = tid&63, qt = tid>>6) computes 8 px
//   -> g_q fp32.
// ---------------------------------------------------------------------------
#define TPX 32
#define NPB (HWP / TPX)          // 72

__global__ __launch_bounds__(256) void proj_kernel(const float* __restrict__ x) {
    __shared__ __align__(16) float xs[CC][TPX];   // 16 KB
    int blk = blockIdx.x;
    int tid = threadIdx.x;

    if (blk < BB * TC * NPB) {
        // ----- context frames -----
        int pb = blk % NPB;
        int t  = (blk / NPB) % TC;
        int b  = blk / (NPB * TC);
        int pix0 = pb * TPX;

        const float* xb = x + ((long)(b * CC) * TT + (t + 1)) * HWP + pix0;
        for (int i = tid; i < CC * TPX; i += 256) {
            int c = i >> 5, px = i & 31;
            xs[c][px] = xb[(long)c * TT * HWP + px];
        }
        __syncthreads();

        int r  = tid & 127;
        int ph = tid >> 7;                  // 16-px half
        u64t acc2[8];
#pragma unroll
        for (int v = 0; v < 8; v++) acc2[v] = 0ull;

#pragma unroll 4
        for (int c = 0; c < CC; c++) {
            float w = g_wcT[c * CC + r];            // coalesced, L1-hot
            u64t w2 = pk2(w, w);
            const ulonglong2* xr = (const ulonglong2*)&xs[c][ph * 16];
#pragma unroll
            for (int v = 0; v < 4; v++) {
                ulonglong2 p = xr[v];
                FMA2(acc2[2*v],     w2, p.x, acc2[2*v]);
                FMA2(acc2[2*v + 1], w2, p.y, acc2[2*v + 1]);
            }
        }

        float af[16];
#pragma unroll
        for (int v = 0; v < 8; v++) upk2(acc2[v], af[2*v], af[2*v+1]);

        if (r < NH) {
            // phi bf16 -> [b][t][pix][h]: lanes r adjacent -> 64B runs
            __nv_bfloat16* ob = g_phi2b
                + ((long)(b * TC + t) * HWP + pix0 + ph * 16) * NH + r;
#pragma unroll
            for (int pp = 0; pp < 16; pp++) ob[pp * NH] = __float2bfloat16(af[pp]);
        } else {
            // g bf16 -> [b][h][t][pix]: 16 contiguous px per thread
            __nv_bfloat16* ob = g_gvTb
                + ((long)(b * NH + (r - NH)) * TC + t) * HWP + pix0 + ph * 16;
#pragma unroll
            for (int pp = 0; pp < 16; pp += 2)
                *(__nv_bfloat162*)(ob + pp) = __floats2bfloat162_rn(af[pp], af[pp+1]);
        }
    } else {
        // ----- query frame: theta -> g_q (fp32) -----
        int blk2 = blk - BB * TC * NPB;
        int pb = blk2 % NPB;
        int b  = blk2 / NPB;
        int pix0 = pb * TPX;

        const float* xb = x + ((long)(b * CC) * TT) * HWP + pix0;
        for (int i = tid; i < CC * TPX; i += 256) {
            int c = i >> 5, px = i & 31;
            xs[c][px] = xb[(long)c * TT * HWP + px];
        }
        __syncthreads();

        int r  = tid & 63;
        int qt = tid >> 6;                 // 8-px quarter
        u64t acc2[4];
#pragma unroll
        for (int v = 0; v < 4; v++) acc2[v] = 0ull;

#pragma unroll 4
        for (int c = 0; c < CC; c++) {
            float w = g_wqT[c * NH + r];
            u64t w2 = pk2(w, w);
            const ulonglong2* xr = (const ulonglong2*)&xs[c][qt * 8];
#pragma unroll
            for (int v = 0; v < 2; v++) {
                ulonglong2 p = xr[v];
                FMA2(acc2[2*v],     w2, p.x, acc2[2*v]);
                FMA2(acc2[2*v + 1], w2, p.y, acc2[2*v + 1]);
            }
        }

        float af[8];
#pragma unroll
        for (int v = 0; v < 4; v++) upk2(acc2[v], af[2*v], af[2*v+1]);

        long base = (long)b * HWP + pix0 + qt * 8;
#pragma unroll
        for (int pp = 0; pp < 8; pp++) g_q[(base + pp) * NH + r] = af[pp];
    }
}

// ---------------------------------------------------------------------------
// Attention per query pixel. Warp-per-key QK on bf16 [t][pix][h] phi (128 B
// per key), softmax fp32, branchless scrambled AV on bf16 [h][t][pix] g.
// block = 256. Writes scrambled Z[b][(p%36)*64+h'][p/36] in fp32.
// ---------------------------------------------------------------------------
__global__ __launch_bounds__(256) void attn_kernel() {
    int bp  = blockIdx.x;               // 0 .. B*HWP-1
    int b   = bp / HWP;
    int pix = bp % HWP;
    int y0  = pix / WW;
    int x0  = pix % WW;
    int tid  = threadIdx.x;
    int warp = tid >> 5;
    int lane = tid & 31;

    __shared__ __align__(16) float qs[NH];
    __shared__ float att[NK];
    __shared__ int   ntp[NK];          // tf*HWP + neighbor pixel
    __shared__ float ypart[4][NH];
    __shared__ float red[16];

    if (tid < NH) qs[tid] = g_q[((long)b * HWP + pix) * NH + tid];

    if (tid < NK) {
        int k   = tid;
        int tf  = k / 49;
        int off = k % 49;
        int dy  = off / 7 - PAD;
        int dx  = off % 7 - PAD;
        int ny  = min(max(y0 + dy, 0), HH - 1);
        int nx  = min(max(x0 + dx, 0), WW - 1);
        ntp[k] = tf * HWP + ny * WW + nx;
    }
    __syncthreads();

    // ---- QK: warp per key; one bf16x2 (4B) load per lane = 128B/key ----
    {
        float2 qv = ((const float2*)qs)[lane];
        const __nv_bfloat16* phib = g_phi2b + (long)b * TC * HWP * NH;
        for (int k = warp; k < NK; k += 8) {
            const __nv_bfloat162* pr = (const __nv_bfloat162*)(phib + ntp[k] * NH);
            float2 a = __bfloat1622float2(pr[lane]);
            float d = qv.x * a.x + qv.y * a.y;
#pragma unroll
            for (int s = 16; s > 0; s >>= 1)
                d += __shfl_xor_sync(0xffffffffu, d, s);
            if (lane == 0) att[k] = d * 8.0f;      // * sqrt(64)
        }
    }
    __syncthreads();

    // ---- softmax over 196 ----
    float v = (tid < NK) ? att[tid] : -1e30f;
    float m = v;
#pragma unroll
    for (int s = 16; s > 0; s >>= 1) m = fmaxf(m, __shfl_xor_sync(0xffffffffu, m, s));
    if (lane == 0) red[warp] = m;
    __syncthreads();
    if (tid == 0) {
        float mm = red[0];
#pragma unroll
        for (int w = 1; w < 8; w++) mm = fmaxf(mm, red[w]);
        red[8] = mm;
    }
    __syncthreads();
    m = red[8];

    float e = (tid < NK) ? __expf(v - m) : 0.f;
    float ssum = e;
#pragma unroll
    for (int s = 16; s > 0; s >>= 1) ssum += __shfl_xor_sync(0xffffffffu, ssum, s);
    if (lane == 0) red[warp] = ssum;
    __syncthreads();
    if (tid == 0) {
        float t2 = red[0];
#pragma unroll
        for (int w = 1; w < 8; w++) t2 += red[w];
        red[9] = 1.f / t2;
    }
    __syncthreads();
    if (tid < NK) att[tid] = e * red[9];
    __syncthreads();

    // ---- AV (scrambled): G[k,h']=g(head=(64k+h')/196, key=(64k+h')%196) ----
    {
        int q = tid >> 6;                 // 0..3
        int h = tid & (NH - 1);
        int kbeg = q * 49;
        const __nv_bfloat16* gbase = g_gvTb + (long)b * NH * FRAME;

        float acc = 0.f;
#pragma unroll 7
        for (int k = kbeg; k < kbeg + 49; k++) {
            int flat = k * NH + h;
            int hh = flat / NK;           // constant divisor -> mul/shift
            int kk = flat - hh * NK;
            acc += att[k] * __bfloat162float(gbase[hh * FRAME + ntp[kk]]);
        }
        ypart[q][h] = acc;
    }
    __syncthreads();
    if (tid < NH) {
        float yv = ypart[0][tid] + ypart[1][tid] + ypart[2][tid] + ypart[3][tid];
        // Y[b,p,h'] -> Z[b, (p%36)*64+h', p/36]
        int p2 = (pix % 36) * 64 + tid;
        int h2 = pix / 36;
        g_z[((long)b * HWP + p2) * NH + h2] = yv;
    }
}

// ---------------------------------------------------------------------------
// Out projection + residual (f32x2, transposed weights, split-h2):
//   out[b,c,p2] = x[b,c,0,p2] + sum_h2 w_out[c,h2] * Z[b,p2,h2]
// block = 256: c = tid&127, kh = tid>>7 (h2 half). 16 pixels per block.
// ---------------------------------------------------------------------------
#define OPX 16
__global__ __launch_bounds__(256) void outproj_kernel(
        const float* __restrict__ x,
        float* __restrict__ out) {
    int blk = blockIdx.x;
    int b   = blk / (HWP / OPX);
    int p20 = (blk % (HWP / OPX)) * OPX;
    int tid = threadIdx.x;
    int c   = tid & 127;
    int kh  = tid >> 7;

    __shared__ __align__(16) float zs[NH][OPX];      // 4 KB  [h2][px]
    __shared__ __align__(16) float part[CC][OPX];    // 8 KB

    for (int i = tid; i < NH * OPX; i += 256) {
        int h2 = i & (NH - 1);                       // coalesced g_z read
        int px = i >> 6;
        zs[h2][px] = g_z[((long)b * HWP + p20 + px) * NH + h2];
    }
    __syncthreads();

    u64t acc2[OPX / 2];
#pragma unroll
    for (int v = 0; v < OPX / 2; v++) acc2[v] = 0ull;

    int h0 = kh * 32;
#pragma unroll 4
    for (int h2 = h0; h2 < h0 + 32; h2++) {
        float w = g_woT[h2 * CC + c];                // lane-consecutive, L1-hot
        u64t w2 = pk2(w, w);
        const ulonglong2* zr = (const ulonglong2*)&zs[h2][0];
#pragma unroll
        for (int v = 0; v < OPX / 4; v++) {
            ulonglong2 p = zr[v];
            FMA2(acc2[2*v],     w2, p.x, acc2[2*v]);
            FMA2(acc2[2*v + 1], w2, p.y, acc2[2*v + 1]);
        }
    }

    float af[OPX];
#pragma unroll
    for (int v = 0; v < OPX / 2; v++) upk2(acc2[v], af[2*v], af[2*v+1]);

    if (kh == 1) {
#pragma unroll
        for (int j = 0; j < OPX; j++) part[c][j] = af[j];
    }
    __syncthreads();
    if (kh == 0) {
        const float* xr   = x   + (((long)(b * CC + c)) * TT + 0) * HWP + p20;
        float*       orow = out + ((long)(b * CC + c)) * HWP + p20;
#pragma unroll
        for (int j = 0; j < OPX; j += 4) {
            float4 xv = *(const float4*)(xr + j);
            *(float4*)(orow + j) = make_float4(
                xv.x + af[j]     + part[c][j],
                xv.y + af[j + 1] + part[c][j + 1],
                xv.z + af[j + 2] + part[c][j + 2],
                xv.w + af[j + 3] + part[c][j + 3]);
        }
    }
}

extern "C" void kernel_launch(void* const* d_in, const int* in_sizes, int n_in,
                              void* d_out, int out_size) {
    const float* x       = (const float*)d_in[0];
    const float* w_theta = (const float*)d_in[1];
    const float* w_phi   = (const float*)d_in[2];
    const float* w_g     = (const float*)d_in[3];
    const float* w_out   = (const float*)d_in[4];
    float* out = (float*)d_out;

    wtrans_kernel<<<128, 256>>>(w_theta, w_phi, w_g, w_out);
    proj_kernel<<<BB * TC * NPB + BB * NPB, 256>>>(x);
    attn_kernel<<<BB * HWP, 256>>>();
    outproj_kernel<<<BB * (HWP / OPX), 256>>>(x, out);
}